// round 14
// baseline (speedup 1.0000x reference)
#include <cuda_runtime.h>
#include <cuda_bf16.h>
#include <cstdint>

#define B_  2
#define T_  2048
#define D_  1024
#define H_  16
#define HD_ 64
#define M_  (B_*T_)   // 4096

// ---------------- scratch ----------------------------------------------------
__device__ __nv_bfloat16 g_xhi[M_*D_], g_xlo[M_*D_];
__device__ __nv_bfloat16 g_whi[4*D_*D_], g_wlo[4*D_*D_];
__device__ __nv_bfloat16 g_qhi[M_*D_], g_qlo[M_*D_];          // [b,h,t,d]
__device__ __nv_bfloat16 g_khi[M_*D_], g_klo[M_*D_];          // [b,h,t,d]
__device__ __nv_bfloat16 g_vthi[M_*D_], g_vtlo[M_*D_];        // [b,h,d,t]
__device__ __nv_bfloat16 g_ohi[M_*D_], g_olo[M_*D_];          // [m, 1024]
__device__ float g_gate[B_*H_*T_];

// ---------------- helpers ----------------------------------------------------
__device__ __forceinline__ uint32_t smem_u32(const void* p) {
    uint32_t a;
    asm("{ .reg .u64 t; cvta.to.shared.u64 t, %1; cvt.u32.u64 %0, t; }" : "=r"(a) : "l"(p));
    return a;
}
__device__ __forceinline__ void cpa16(uint32_t dst, const void* src) {
    asm volatile("cp.async.cg.shared.global [%0], [%1], 16;" :: "r"(dst), "l"(src));
}
#define CP_COMMIT() asm volatile("cp.async.commit_group;" ::: "memory")
#define CP_WAIT0()  asm volatile("cp.async.wait_group 0;" ::: "memory")
#define CP_WAIT1()  asm volatile("cp.async.wait_group 1;" ::: "memory")

__device__ __forceinline__ void ldm4(uint32_t* r, uint32_t addr) {
    asm volatile("ldmatrix.sync.aligned.m8n8.x4.shared.b16 {%0,%1,%2,%3}, [%4];"
                 : "=r"(r[0]), "=r"(r[1]), "=r"(r[2]), "=r"(r[3]) : "r"(addr));
}
__device__ __forceinline__ void mma_bf16(float* d, const uint32_t* a, const uint32_t* b) {
    asm volatile("mma.sync.aligned.m16n8k16.row.col.f32.bf16.bf16.f32 "
                 "{%0,%1,%2,%3}, {%4,%5,%6,%7}, {%8,%9}, {%0,%1,%2,%3};"
                 : "+f"(d[0]), "+f"(d[1]), "+f"(d[2]), "+f"(d[3])
                 : "r"(a[0]), "r"(a[1]), "r"(a[2]), "r"(a[3]), "r"(b[0]), "r"(b[1]));
}

__device__ __forceinline__ void split2(float v, unsigned short& h, unsigned short& l) {
    __nv_bfloat16 hb = __float2bfloat16(v);
    h = __bfloat16_as_ushort(hb);
    l = __bfloat16_as_ushort(__float2bfloat16(v - __bfloat162float(hb)));
}
__device__ __forceinline__ void pack8(const float* v, uint4& uh, uint4& ul) {
    unsigned short h[8], l[8];
    #pragma unroll
    for (int j = 0; j < 8; j++) split2(v[j], h[j], l[j]);
    uh = make_uint4((uint32_t)h[0] | ((uint32_t)h[1] << 16), (uint32_t)h[2] | ((uint32_t)h[3] << 16),
                    (uint32_t)h[4] | ((uint32_t)h[5] << 16), (uint32_t)h[6] | ((uint32_t)h[7] << 16));
    ul = make_uint4((uint32_t)l[0] | ((uint32_t)l[1] << 16), (uint32_t)l[2] | ((uint32_t)l[3] << 16),
                    (uint32_t)l[4] | ((uint32_t)l[5] << 16), (uint32_t)l[6] | ((uint32_t)l[7] << 16));
}

// ---------------- conversions ------------------------------------------------
__global__ void __launch_bounds__(256) cvt_x(const float* __restrict__ src) {
    int i = (blockIdx.x * 256 + threadIdx.x) * 4;
    float4 v = *(const float4*)(src + i);
    unsigned short h[4], l[4];
    split2(v.x, h[0], l[0]); split2(v.y, h[1], l[1]);
    split2(v.z, h[2], l[2]); split2(v.w, h[3], l[3]);
    *(uint2*)(g_xhi + i) = make_uint2((uint32_t)h[0] | ((uint32_t)h[1] << 16),
                                      (uint32_t)h[2] | ((uint32_t)h[3] << 16));
    *(uint2*)(g_xlo + i) = make_uint2((uint32_t)l[0] | ((uint32_t)l[1] << 16),
                                      (uint32_t)l[2] | ((uint32_t)l[3] << 16));
}
__global__ void __launch_bounds__(256) cvt_w(const float* __restrict__ src, int w) {
    int i = (blockIdx.x * 256 + threadIdx.x) * 4;
    float4 v = *(const float4*)(src + i);
    unsigned short h[4], l[4];
    split2(v.x, h[0], l[0]); split2(v.y, h[1], l[1]);
    split2(v.z, h[2], l[2]); split2(v.w, h[3], l[3]);
    *(uint2*)(g_whi + (size_t)w * D_ * D_ + i) = make_uint2((uint32_t)h[0] | ((uint32_t)h[1] << 16),
                                                            (uint32_t)h[2] | ((uint32_t)h[3] << 16));
    *(uint2*)(g_wlo + (size_t)w * D_ * D_ + i) = make_uint2((uint32_t)l[0] | ((uint32_t)l[1] << 16),
                                                            (uint32_t)l[2] | ((uint32_t)l[3] << 16));
}

// ---------------- mma.sync GEMM ----------------------------------------------
// C = A @ W^T + bias.  modes: 0->g_q, 1->g_k ([b,h,t,d] split),
// 2->g_vt ([b,h,d,t] split, transposed epilogue), 3: A:=g_o, fp32 out.
// CTA 128x128, K-chunk 32, 8 warps (wy 0-1 x wx 0-3), warp tile 64x32.
// smem tile stride 40 el (80 B): 16B aligned.
#define GS_TILE 10240          // 128*40*2
#define GS_BUF  40960          // 4 tiles
#define GS_SMEM 81920          // 2 buffers (C staging 128*132*4=67584 reuses it)

__global__ void __launch_bounds__(256) mm_gemm(const float* __restrict__ bias,
                                               float* __restrict__ outp, int mode)
{
    extern __shared__ char smc[];
    const uint32_t sb = smem_u32(smc);
    __shared__ float bias_s[128];

    const int bn = blockIdx.x * 128, bm = blockIdx.y * 128;
    const int tid = threadIdx.x, lane = tid & 31, wid = tid >> 5;
    const int wy = wid >> 2, wx = wid & 3;
    const int g = lane >> 2, tig = lane & 3;

    if (tid < 128) bias_s[tid] = bias[bn + tid];

    const __nv_bfloat16* Ah = (mode == 3) ? g_ohi : g_xhi;
    const __nv_bfloat16* Al = (mode == 3) ? g_olo : g_xlo;
    const int widx = (mode == 3) ? 3 : mode;
    const __nv_bfloat16* Wh = g_whi + (size_t)widx * D_ * D_;
    const __nv_bfloat16* Wl = g_wlo + (size_t)widx * D_ * D_;

    float acc[4][4][4] = {};

    // -- prologue: chunk 0 into buffer 0
    #pragma unroll
    for (int j = 0; j < 8; j++) {
        int c = tid + j * 256;
        int tl = c >> 9, idx = c & 511, row = idx >> 2, sg = idx & 3;
        const __nv_bfloat16* bp = (tl == 0) ? Ah : (tl == 1) ? Al : (tl == 2) ? Wh : Wl;
        int gr = ((tl < 2) ? bm : bn) + row;
        cpa16(sb + tl * GS_TILE + row * 80 + sg * 16, bp + (size_t)gr * 1024 + sg * 8);
    }
    CP_COMMIT();

    for (int it = 0; it < 32; it++) {
        const int buf = it & 1;
        if (it + 1 < 32) {
            const int k0 = (it + 1) * 32;
            const int nb = buf ^ 1;
            #pragma unroll
            for (int j = 0; j < 8; j++) {
                int c = tid + j * 256;
                int tl = c >> 9, idx = c & 511, row = idx >> 2, sg = idx & 3;
                const __nv_bfloat16* bp = (tl == 0) ? Ah : (tl == 1) ? Al : (tl == 2) ? Wh : Wl;
                int gr = ((tl < 2) ? bm : bn) + row;
                cpa16(sb + nb * GS_BUF + tl * GS_TILE + row * 80 + sg * 16,
                      bp + (size_t)gr * 1024 + k0 + sg * 8);
            }
            CP_COMMIT();
            CP_WAIT1();
        } else {
            CP_WAIT0();
        }
        __syncthreads();

        const uint32_t bb = sb + buf * GS_BUF;
        #pragma unroll
        for (int kt = 0; kt < 2; kt++) {
            uint32_t ahf[4][4], alf[4][4];
            const uint32_t arow = wy * 64 + (lane & 15);
            const uint32_t acol = (kt * 16 + (lane >> 4) * 8) * 2;
            #pragma unroll
            for (int mt = 0; mt < 4; mt++) {
                ldm4(ahf[mt], bb + 0 * GS_TILE + (arow + mt * 16) * 80 + acol);
                ldm4(alf[mt], bb + 1 * GS_TILE + (arow + mt * 16) * 80 + acol);
            }
            #pragma unroll
            for (int np = 0; np < 2; np++) {
                uint32_t bhf[4], blf[4];
                const uint32_t brow = wx * 32 + np * 16 + (lane & 7) + ((lane >> 4) & 1) * 8;
                const uint32_t bcol = (kt * 16 + ((lane >> 3) & 1) * 8) * 2;
                ldm4(bhf, bb + 2 * GS_TILE + brow * 80 + bcol);
                ldm4(blf, bb + 3 * GS_TILE + brow * 80 + bcol);
                #pragma unroll
                for (int mt = 0; mt < 4; mt++) {
                    #pragma unroll
                    for (int hn = 0; hn < 2; hn++) {
                        const int nt = np * 2 + hn;
                        mma_bf16(acc[mt][nt], ahf[mt], bhf + hn * 2);
                        mma_bf16(acc[mt][nt], ahf[mt], blf + hn * 2);
                        mma_bf16(acc[mt][nt], alf[mt], bhf + hn * 2);
                    }
                }
            }
        }
        __syncthreads();
    }

    // ---- stage C (fp32, stride 132) ----
    float* Cs = (float*)smc;
    #pragma unroll
    for (int mt = 0; mt < 4; mt++) {
        const int r0 = wy * 64 + mt * 16 + g;
        #pragma unroll
        for (int nt = 0; nt < 4; nt++) {
            const int cc = wx * 32 + nt * 8 + tig * 2;
            *(float2*)(Cs + r0 * 132 + cc)       = make_float2(acc[mt][nt][0], acc[mt][nt][1]);
            *(float2*)(Cs + (r0 + 8) * 132 + cc) = make_float2(acc[mt][nt][2], acc[mt][nt][3]);
        }
    }
    __syncthreads();

    if (mode <= 1) {
        __nv_bfloat16* dh = (mode == 0) ? g_qhi : g_khi;
        __nv_bfloat16* dl = (mode == 0) ? g_qlo : g_klo;
        const int row = tid >> 1, half = tid & 1;
        const int m = bm + row;
        const int bbk = m >> 11, t = m & 2047;
        const int head = (bn >> 6) + half;
        const size_t ro = ((size_t)(bbk * H_ + head) * T_ + t) * HD_;
        float vals[64];
        #pragma unroll
        for (int j = 0; j < 64; j++) vals[j] = Cs[row * 132 + half * 64 + j] + bias_s[half * 64 + j];
        #pragma unroll
        for (int blk = 0; blk < 8; blk++) {
            uint4 uh, ul;
            pack8(&vals[blk * 8], uh, ul);
            *(uint4*)(dh + ro + blk * 8) = uh;
            *(uint4*)(dl + ro + blk * 8) = ul;
        }
    } else if (mode == 3) {
        const int row = tid >> 1, half = tid & 1;
        const int m = bm + row;
        #pragma unroll
        for (int j4 = 0; j4 < 16; j4++) {
            float4 o;
            o.x = Cs[row * 132 + half * 64 + j4 * 4 + 0] + bias_s[half * 64 + j4 * 4 + 0];
            o.y = Cs[row * 132 + half * 64 + j4 * 4 + 1] + bias_s[half * 64 + j4 * 4 + 1];
            o.z = Cs[row * 132 + half * 64 + j4 * 4 + 2] + bias_s[half * 64 + j4 * 4 + 2];
            o.w = Cs[row * 132 + half * 64 + j4 * 4 + 3] + bias_s[half * 64 + j4 * 4 + 3];
            *(float4*)(outp + (size_t)m * 1024 + bn + half * 64 + j4 * 4) = o;
        }
    } else {
        // mode 2: transposed write [b,h,d,t]
        const int nl = tid >> 1, mhalf = tid & 1;
        const int n = bn + nl;
        const int head = n >> 6, d = n & 63;
        const int bbk = bm >> 11;
        const float bia = bias_s[nl];
        float vals[64];
        #pragma unroll
        for (int j = 0; j < 64; j++) vals[j] = Cs[(mhalf * 64 + j) * 132 + nl] + bia;
        __nv_bfloat16* dsth = g_vthi + ((size_t)(bbk * H_ + head) * HD_ + d) * T_ + (bm & 2047) + mhalf * 64;
        __nv_bfloat16* dstl = g_vtlo + ((size_t)(bbk * H_ + head) * HD_ + d) * T_ + (bm & 2047) + mhalf * 64;
        #pragma unroll
        for (int blk = 0; blk < 8; blk++) {
            uint4 uh, ul;
            pack8(&vals[blk * 8], uh, ul);
            *(uint4*)(dsth + blk * 8) = uh;
            *(uint4*)(dstl + blk * 8) = ul;
        }
    }
}

// ---------------- gate --------------------------------------------------------
__global__ void __launch_bounds__(256) gate_kernel(const float* __restrict__ x,
                                                   const float* __restrict__ Wg,
                                                   const float* __restrict__ bg,
                                                   const float* __restrict__ gc)
{
    __shared__ float wgs[512];
    __shared__ float bgs[8];
    for (int i = threadIdx.x; i < 512; i += 256) wgs[i] = Wg[i];
    if (threadIdx.x < 8) bgs[threadIdx.x] = bg[threadIdx.x];
    __syncthreads();

    const int idx = blockIdx.x * 256 + threadIdx.x;
    const int b = idx >> 15, h = (idx >> 11) & 15, t = idx & 2047;
    const float* xr = x + ((size_t)(b * T_ + t)) * D_ + h * HD_;
    float xv[64];
    #pragma unroll
    for (int i = 0; i < 16; i++) *(float4*)&xv[i * 4] = *(const float4*)(xr + i * 4);

    float s0 = 0.f, s1 = 0.f;
    #pragma unroll
    for (int e = 0; e < 8; e++) {
        float s = bgs[e];
        #pragma unroll
        for (int d = 0; d < 64; d++) s += xv[d] * wgs[e * 64 + d];
        if (e < 4) s0 += s; else s1 += s;
    }
    const float g0 = 1.f / (1.f + __expf(-s0));
    const float g1 = 1.f / (1.f + __expf(-s1));
    g_gate[idx] = g0 * (g1 * gc[h] - 1.0f) + 2.0f;
}

// ---------------- mma.sync attention ------------------------------------------
// smem (bytes): Q hi/lo (stride 144B) @0/18432; K hi/lo @36864/55296;
// Vt hi/lo (stride 272B) @73728/91136; P hi/lo (stride 272B) @108544/143360.
#define A_Q   0
#define A_K   36864
#define A_VT  73728
#define A_P   108544
#define A_SMEM 178176

__global__ void __launch_bounds__(256) attn_mm(const float* __restrict__ pb)
{
    extern __shared__ char smc[];
    const uint32_t sb = smem_u32(smc);
    __shared__ float gate_s[128];
    __shared__ float l_smem[128];

    const int b  = blockIdx.x & 1;
    const int q0 = (blockIdx.x >> 1) * 128;
    const int h  = blockIdx.y;
    const int bh = b * H_ + h;
    const int tid = threadIdx.x, lane = tid & 31, wid = tid >> 5;
    const int wy = wid >> 2, wx = wid & 3;
    const int g = lane >> 2, tig = lane & 3;

    if (tid < 128) {
        gate_s[tid] = g_gate[bh * T_ + q0 + tid];
        l_smem[tid] = 0.f;
    }

    // Q load (cp.async, 2048 uint4)
    #pragma unroll
    for (int j = 0; j < 8; j++) {
        int c = tid + j * 256;
        int arr = c >> 10, idx = c & 1023, row = idx >> 3, sg = idx & 7;
        cpa16(sb + A_Q + arr * 18432 + row * 144 + sg * 16,
              (arr ? g_qlo : g_qhi) + ((size_t)bh * T_ + q0 + row) * HD_ + sg * 8);
    }
    CP_COMMIT();

    float oacc[4][2][4] = {};
    float l_acc[8] = {};

    for (int kb = 0; kb < 16; kb++) {
        __syncthreads();          // prior PV readers done before K/Vt overwrite
        #pragma unroll
        for (int j = 0; j < 8; j++) {     // K hi/lo
            int c = tid + j * 256;
            int arr = c >> 10, idx = c & 1023, row = idx >> 3, sg = idx & 7;
            cpa16(sb + A_K + arr * 18432 + row * 144 + sg * 16,
                  (arr ? g_klo : g_khi) + ((size_t)bh * T_ + kb * 128 + row) * HD_ + sg * 8);
        }
        #pragma unroll
        for (int j = 0; j < 8; j++) {     // Vt hi/lo
            int c = tid + j * 256;
            int arr = c >> 10, idx = c & 1023, row = idx >> 4, sg = idx & 15;
            cpa16(sb + A_VT + arr * 17408 + row * 272 + sg * 16,
                  (arr ? g_vtlo : g_vthi) + ((size_t)bh * HD_ + row) * T_ + kb * 128 + sg * 8);
        }
        CP_COMMIT(); CP_WAIT0();
        __syncthreads();

        // ---- S = Q K^T (3 products) ----
        float sacc[4][4][4] = {};
        #pragma unroll
        for (int kt = 0; kt < 4; kt++) {
            uint32_t qh[4][4], ql[4][4];
            const uint32_t arow = wy * 64 + (lane & 15);
            const uint32_t acol = (kt * 16 + (lane >> 4) * 8) * 2;
            #pragma unroll
            for (int mt = 0; mt < 4; mt++) {
                ldm4(qh[mt], sb + A_Q + (arow + mt * 16) * 144 + acol);
                ldm4(ql[mt], sb + A_Q + 18432 + (arow + mt * 16) * 144 + acol);
            }
            #pragma unroll
            for (int np = 0; np < 2; np++) {
                uint32_t kh[4], kl[4];
                const uint32_t brow = wx * 32 + np * 16 + (lane & 7) + ((lane >> 4) & 1) * 8;
                const uint32_t bcol = (kt * 16 + ((lane >> 3) & 1) * 8) * 2;
                ldm4(kh, sb + A_K + brow * 144 + bcol);
                ldm4(kl, sb + A_K + 18432 + brow * 144 + bcol);
                #pragma unroll
                for (int mt = 0; mt < 4; mt++) {
                    #pragma unroll
                    for (int hn = 0; hn < 2; hn++) {
                        const int nt = np * 2 + hn;
                        mma_bf16(sacc[mt][nt], qh[mt], kh + hn * 2);
                        mma_bf16(sacc[mt][nt], qh[mt], kl + hn * 2);
                        mma_bf16(sacc[mt][nt], ql[mt], kh + hn * 2);
                    }
                }
            }
        }

        // ---- epilogue: exp(0.125 s + gate*bias) -> split-bf16 P in smem ----
        #pragma unroll
        for (int mt = 0; mt < 4; mt++) {
            #pragma unroll
            for (int rh = 0; rh < 2; rh++) {
                const int row = wy * 64 + mt * 16 + g + rh * 8;
                const float gt = gate_s[row];
                const float* brow = pb + ((size_t)h * T_ + q0 + row) * T_ + kb * 128;
                float lsum = 0.f;
                #pragma unroll
                for (int nt = 0; nt < 4; nt++) {
                    const int col = wx * 32 + nt * 8 + tig * 2;
                    float2 bv = *(const float2*)(brow + col);
                    float p0 = __expf(sacc[mt][nt][rh * 2 + 0] * 0.125f + gt * bv.x);
                    float p1 = __expf(sacc[mt][nt][rh * 2 + 1] * 0.125f + gt * bv.y);
                    lsum += p0 + p1;
                    unsigned short h0, l0, h1, l1;
                    split2(p0, h0, l0); split2(p1, h1, l1);
                    *(uint32_t*)(smc + A_P + row * 272 + col * 2) =
                        (uint32_t)h0 | ((uint32_t)h1 << 16);
                    *(uint32_t*)(smc + A_P + 34816 + row * 272 + col * 2) =
                        (uint32_t)l0 | ((uint32_t)l1 << 16);
                }
                l_acc[mt * 2 + rh] += lsum;
            }
        }
        __syncthreads();

        // ---- O += P V (3 products) ----
        #pragma unroll
        for (int kt = 0; kt < 8; kt++) {
            uint32_t ph[4][4], pl[4][4];
            const uint32_t arow = wy * 64 + (lane & 15);
            const uint32_t acol = (kt * 16 + (lane >> 4) * 8) * 2;
            #pragma unroll
            for (int mt = 0; mt < 4; mt++) {
                ldm4(ph[mt], sb + A_P + (arow + mt * 16) * 272 + acol);
                ldm4(pl[mt], sb + A_P + 34816 + (arow + mt * 16) * 272 + acol);
            }
            uint32_t vh[4], vl[4];
            const uint32_t brow = wx * 16 + (lane & 7) + ((lane >> 4) & 1) * 8;
            const uint32_t bcol = (kt * 16 + ((lane >> 3) & 1) * 8) * 2;
            ldm4(vh, sb + A_VT + brow * 272 + bcol);
            ldm4(vl, sb + A_VT + 17408 + brow * 272 + bcol);
            #pragma unroll
            for (int mt = 0; mt < 4; mt++) {
                #pragma unroll
                for (int hn = 0; hn < 2; hn++) {
                    mma_bf16(oacc[mt][hn], ph[mt], vh + hn * 2);
                    mma_bf16(oacc[mt][hn], ph[mt], vl + hn * 2);
                    mma_bf16(oacc[mt][hn], pl[mt], vh + hn * 2);
                }
            }
        }
    }

    // ---- l reduction ----
    #pragma unroll
    for (int i = 0; i < 8; i++) {
        l_acc[i] += __shfl_xor_sync(0xffffffffu, l_acc[i], 1);
        l_acc[i] += __shfl_xor_sync(0xffffffffu, l_acc[i], 2);
    }
    __syncthreads();
    if (tig == 0) {
        #pragma unroll
        for (int mt = 0; mt < 4; mt++) {
            #pragma unroll
            for (int rh = 0; rh < 2; rh++)
                atomicAdd(&l_smem[wy * 64 + mt * 16 + g + rh * 8], l_acc[mt * 2 + rh]);
        }
    }
    __syncthreads();

    // ---- write O (split bf16) ----
    #pragma unroll
    for (int mt = 0; mt < 4; mt++) {
        #pragma unroll
        for (int rh = 0; rh < 2; rh++) {
            const int row = wy * 64 + mt * 16 + g + rh * 8;
            const float inv = 1.0f / l_smem[row];
            const size_t ro = (size_t)(b * T_ + q0 + row) * 1024 + h * 64;
            #pragma unroll
            for (int nt = 0; nt < 2; nt++) {
                const int d0 = wx * 16 + nt * 8 + tig * 2;
                float v0 = oacc[mt][nt][rh * 2 + 0] * inv;
                float v1 = oacc[mt][nt][rh * 2 + 1] * inv;
                unsigned short h0, l0, h1, l1;
                split2(v0, h0, l0); split2(v1, h1, l1);
                *(uint32_t*)(g_ohi + ro + d0) = (uint32_t)h0 | ((uint32_t)h1 << 16);
                *(uint32_t*)(g_olo + ro + d0) = (uint32_t)l0 | ((uint32_t)l1 << 16);
            }
        }
    }
}

// ---------------- launch ------------------------------------------------------
extern "C" void kernel_launch(void* const* d_in, const int* in_sizes, int n_in,
                              void* d_out, int out_size)
{
    const float* x  = (const float*)d_in[0];
    const float* pb = (const float*)d_in[1];
    const float* Wq = (const float*)d_in[2];
    const float* bq = (const float*)d_in[3];
    const float* Wk = (const float*)d_in[4];
    const float* bk = (const float*)d_in[5];
    const float* Wv = (const float*)d_in[6];
    const float* bv = (const float*)d_in[7];
    const float* Wo = (const float*)d_in[8];
    const float* bo = (const float*)d_in[9];
    const float* Wg = (const float*)d_in[10];
    const float* bg = (const float*)d_in[11];
    const float* gc = (const float*)d_in[12];
    float* out = (float*)d_out;

    cudaFuncSetAttribute(mm_gemm, cudaFuncAttributeMaxDynamicSharedMemorySize, GS_SMEM);
    cudaFuncSetAttribute(attn_mm, cudaFuncAttributeMaxDynamicSharedMemorySize, A_SMEM);

    cvt_x<<<M_*D_/1024, 256>>>(x);
    cvt_w<<<D_*D_/1024, 256>>>(Wq, 0);
    cvt_w<<<D_*D_/1024, 256>>>(Wk, 1);
    cvt_w<<<D_*D_/1024, 256>>>(Wv, 2);
    cvt_w<<<D_*D_/1024, 256>>>(Wo, 3);
    gate_kernel<<<(B_*H_*T_)/256, 256>>>(x, Wg, bg, gc);

    dim3 gg(D_/128, M_/128);
    mm_gemm<<<gg, 256, GS_SMEM>>>(bq, nullptr, 0);
    mm_gemm<<<gg, 256, GS_SMEM>>>(bk, nullptr, 1);
    mm_gemm<<<gg, 256, GS_SMEM>>>(bv, nullptr, 2);

    attn_mm<<<dim3((T_/128)*B_, H_), 256, A_SMEM>>>(pb);

    mm_gemm<<<gg, 256, GS_SMEM>>>(bo, out, 3);
}

// round 15
// speedup vs baseline: 1.0011x; 1.0011x over previous
#include <cuda_runtime.h>
#include <cuda_bf16.h>
#include <cstdint>

#define B_  2
#define T_  2048
#define D_  1024
#define H_  16
#define HD_ 64
#define M_  (B_*T_)   // 4096

// ---------------- scratch ----------------------------------------------------
__device__ __nv_bfloat16 g_xhi[M_*D_], g_xlo[M_*D_];
__device__ __nv_bfloat16 g_whi[4*D_*D_], g_wlo[4*D_*D_];
__device__ __nv_bfloat16 g_qhi[M_*D_], g_qlo[M_*D_];          // [b,h,t,d]
__device__ __nv_bfloat16 g_khi[M_*D_], g_klo[M_*D_];          // [b,h,t,d]
__device__ __nv_bfloat16 g_vthi[M_*D_], g_vtlo[M_*D_];        // [b,h,d,t]
__device__ __nv_bfloat16 g_ohi[M_*D_], g_olo[M_*D_];          // [m, 1024]
__device__ float g_gate[B_*H_*T_];

// ---------------- helpers ----------------------------------------------------
__device__ __forceinline__ uint32_t smem_u32(const void* p) {
    uint32_t a;
    asm("{ .reg .u64 t; cvta.to.shared.u64 t, %1; cvt.u32.u64 %0, t; }" : "=r"(a) : "l"(p));
    return a;
}
__device__ __forceinline__ void cpa16(uint32_t dst, const void* src) {
    asm volatile("cp.async.cg.shared.global [%0], [%1], 16;" :: "r"(dst), "l"(src));
}
#define CP_COMMIT() asm volatile("cp.async.commit_group;" ::: "memory")
#define CP_WAIT0()  asm volatile("cp.async.wait_group 0;" ::: "memory")
#define CP_WAIT1()  asm volatile("cp.async.wait_group 1;" ::: "memory")

__device__ __forceinline__ void ldm4(uint32_t* r, uint32_t addr) {
    asm volatile("ldmatrix.sync.aligned.m8n8.x4.shared.b16 {%0,%1,%2,%3}, [%4];"
                 : "=r"(r[0]), "=r"(r[1]), "=r"(r[2]), "=r"(r[3]) : "r"(addr));
}
__device__ __forceinline__ void mma_bf16(float* d, const uint32_t* a, const uint32_t* b) {
    asm volatile("mma.sync.aligned.m16n8k16.row.col.f32.bf16.bf16.f32 "
                 "{%0,%1,%2,%3}, {%4,%5,%6,%7}, {%8,%9}, {%0,%1,%2,%3};"
                 : "+f"(d[0]), "+f"(d[1]), "+f"(d[2]), "+f"(d[3])
                 : "r"(a[0]), "r"(a[1]), "r"(a[2]), "r"(a[3]), "r"(b[0]), "r"(b[1]));
}

__device__ __forceinline__ void split2(float v, unsigned short& h, unsigned short& l) {
    __nv_bfloat16 hb = __float2bfloat16(v);
    h = __bfloat16_as_ushort(hb);
    l = __bfloat16_as_ushort(__float2bfloat16(v - __bfloat162float(hb)));
}
__device__ __forceinline__ void pack8(const float* v, uint4& uh, uint4& ul) {
    unsigned short h[8], l[8];
    #pragma unroll
    for (int j = 0; j < 8; j++) split2(v[j], h[j], l[j]);
    uh = make_uint4((uint32_t)h[0] | ((uint32_t)h[1] << 16), (uint32_t)h[2] | ((uint32_t)h[3] << 16),
                    (uint32_t)h[4] | ((uint32_t)h[5] << 16), (uint32_t)h[6] | ((uint32_t)h[7] << 16));
    ul = make_uint4((uint32_t)l[0] | ((uint32_t)l[1] << 16), (uint32_t)l[2] | ((uint32_t)l[3] << 16),
                    (uint32_t)l[4] | ((uint32_t)l[5] << 16), (uint32_t)l[6] | ((uint32_t)l[7] << 16));
}

// ---------------- conversions ------------------------------------------------
__global__ void __launch_bounds__(256) cvt_x(const float* __restrict__ src) {
    int i = (blockIdx.x * 256 + threadIdx.x) * 4;
    float4 v = *(const float4*)(src + i);
    unsigned short h[4], l[4];
    split2(v.x, h[0], l[0]); split2(v.y, h[1], l[1]);
    split2(v.z, h[2], l[2]); split2(v.w, h[3], l[3]);
    *(uint2*)(g_xhi + i) = make_uint2((uint32_t)h[0] | ((uint32_t)h[1] << 16),
                                      (uint32_t)h[2] | ((uint32_t)h[3] << 16));
    *(uint2*)(g_xlo + i) = make_uint2((uint32_t)l[0] | ((uint32_t)l[1] << 16),
                                      (uint32_t)l[2] | ((uint32_t)l[3] << 16));
}
__global__ void __launch_bounds__(256) cvt_w(const float* __restrict__ src, int w) {
    int i = (blockIdx.x * 256 + threadIdx.x) * 4;
    float4 v = *(const float4*)(src + i);
    unsigned short h[4], l[4];
    split2(v.x, h[0], l[0]); split2(v.y, h[1], l[1]);
    split2(v.z, h[2], l[2]); split2(v.w, h[3], l[3]);
    *(uint2*)(g_whi + (size_t)w * D_ * D_ + i) = make_uint2((uint32_t)h[0] | ((uint32_t)h[1] << 16),
                                                            (uint32_t)h[2] | ((uint32_t)h[3] << 16));
    *(uint2*)(g_wlo + (size_t)w * D_ * D_ + i) = make_uint2((uint32_t)l[0] | ((uint32_t)l[1] << 16),
                                                            (uint32_t)l[2] | ((uint32_t)l[3] << 16));
}

// ---------------- mma.sync GEMM ----------------------------------------------
// C = A @ W^T + bias.  modes: 0->g_q, 1->g_k ([b,h,t,d] split),
// 2->g_vt ([b,h,d,t] split, transposed epilogue), 3: A:=g_o, fp32 out.
// CTA 128x128, K-chunk 32, 8 warps (wy 0-1 x wx 0-3), warp tile 64x32.
// smem tile stride 40 el (80 B): 16B aligned.
#define GS_TILE 10240          // 128*40*2
#define GS_BUF  40960          // 4 tiles
#define GS_SMEM 81920          // 2 buffers (C staging 128*132*4=67584 reuses it)

__global__ void __launch_bounds__(256) mm_gemm(const float* __restrict__ bias,
                                               float* __restrict__ outp, int mode)
{
    extern __shared__ char smc[];
    const uint32_t sb = smem_u32(smc);
    __shared__ float bias_s[128];

    const int bn = blockIdx.x * 128, bm = blockIdx.y * 128;
    const int tid = threadIdx.x, lane = tid & 31, wid = tid >> 5;
    const int wy = wid >> 2, wx = wid & 3;
    const int g = lane >> 2, tig = lane & 3;

    if (tid < 128) bias_s[tid] = bias[bn + tid];

    const __nv_bfloat16* Ah = (mode == 3) ? g_ohi : g_xhi;
    const __nv_bfloat16* Al = (mode == 3) ? g_olo : g_xlo;
    const int widx = (mode == 3) ? 3 : mode;
    const __nv_bfloat16* Wh = g_whi + (size_t)widx * D_ * D_;
    const __nv_bfloat16* Wl = g_wlo + (size_t)widx * D_ * D_;

    float acc[4][4][4] = {};

    // -- prologue: chunk 0 into buffer 0
    #pragma unroll
    for (int j = 0; j < 8; j++) {
        int c = tid + j * 256;
        int tl = c >> 9, idx = c & 511, row = idx >> 2, sg = idx & 3;
        const __nv_bfloat16* bp = (tl == 0) ? Ah : (tl == 1) ? Al : (tl == 2) ? Wh : Wl;
        int gr = ((tl < 2) ? bm : bn) + row;
        cpa16(sb + tl * GS_TILE + row * 80 + sg * 16, bp + (size_t)gr * 1024 + sg * 8);
    }
    CP_COMMIT();

    for (int it = 0; it < 32; it++) {
        const int buf = it & 1;
        if (it + 1 < 32) {
            const int k0 = (it + 1) * 32;
            const int nb = buf ^ 1;
            #pragma unroll
            for (int j = 0; j < 8; j++) {
                int c = tid + j * 256;
                int tl = c >> 9, idx = c & 511, row = idx >> 2, sg = idx & 3;
                const __nv_bfloat16* bp = (tl == 0) ? Ah : (tl == 1) ? Al : (tl == 2) ? Wh : Wl;
                int gr = ((tl < 2) ? bm : bn) + row;
                cpa16(sb + nb * GS_BUF + tl * GS_TILE + row * 80 + sg * 16,
                      bp + (size_t)gr * 1024 + k0 + sg * 8);
            }
            CP_COMMIT();
            CP_WAIT1();
        } else {
            CP_WAIT0();
        }
        __syncthreads();

        const uint32_t bb = sb + buf * GS_BUF;
        #pragma unroll
        for (int kt = 0; kt < 2; kt++) {
            uint32_t ahf[4][4], alf[4][4];
            const uint32_t arow = wy * 64 + (lane & 15);
            const uint32_t acol = (kt * 16 + (lane >> 4) * 8) * 2;
            #pragma unroll
            for (int mt = 0; mt < 4; mt++) {
                ldm4(ahf[mt], bb + 0 * GS_TILE + (arow + mt * 16) * 80 + acol);
                ldm4(alf[mt], bb + 1 * GS_TILE + (arow + mt * 16) * 80 + acol);
            }
            #pragma unroll
            for (int np = 0; np < 2; np++) {
                uint32_t bhf[4], blf[4];
                const uint32_t brow = wx * 32 + np * 16 + (lane & 7) + ((lane >> 4) & 1) * 8;
                const uint32_t bcol = (kt * 16 + ((lane >> 3) & 1) * 8) * 2;
                ldm4(bhf, bb + 2 * GS_TILE + brow * 80 + bcol);
                ldm4(blf, bb + 3 * GS_TILE + brow * 80 + bcol);
                #pragma unroll
                for (int mt = 0; mt < 4; mt++) {
                    #pragma unroll
                    for (int hn = 0; hn < 2; hn++) {
                        const int nt = np * 2 + hn;
                        mma_bf16(acc[mt][nt], ahf[mt], bhf + hn * 2);
                        mma_bf16(acc[mt][nt], ahf[mt], blf + hn * 2);
                        mma_bf16(acc[mt][nt], alf[mt], bhf + hn * 2);
                    }
                }
            }
        }
        __syncthreads();
    }

    // ---- stage C (fp32, stride 132) ----
    float* Cs = (float*)smc;
    #pragma unroll
    for (int mt = 0; mt < 4; mt++) {
        const int r0 = wy * 64 + mt * 16 + g;
        #pragma unroll
        for (int nt = 0; nt < 4; nt++) {
            const int cc = wx * 32 + nt * 8 + tig * 2;
            *(float2*)(Cs + r0 * 132 + cc)       = make_float2(acc[mt][nt][0], acc[mt][nt][1]);
            *(float2*)(Cs + (r0 + 8) * 132 + cc) = make_float2(acc[mt][nt][2], acc[mt][nt][3]);
        }
    }
    __syncthreads();

    if (mode <= 1) {
        __nv_bfloat16* dh = (mode == 0) ? g_qhi : g_khi;
        __nv_bfloat16* dl = (mode == 0) ? g_qlo : g_klo;
        const int row = tid >> 1, half = tid & 1;
        const int m = bm + row;
        const int bbk = m >> 11, t = m & 2047;
        const int head = (bn >> 6) + half;
        const size_t ro = ((size_t)(bbk * H_ + head) * T_ + t) * HD_;
        float vals[64];
        #pragma unroll
        for (int j = 0; j < 64; j++) vals[j] = Cs[row * 132 + half * 64 + j] + bias_s[half * 64 + j];
        #pragma unroll
        for (int blk = 0; blk < 8; blk++) {
            uint4 uh, ul;
            pack8(&vals[blk * 8], uh, ul);
            *(uint4*)(dh + ro + blk * 8) = uh;
            *(uint4*)(dl + ro + blk * 8) = ul;
        }
    } else if (mode == 3) {
        const int row = tid >> 1, half = tid & 1;
        const int m = bm + row;
        #pragma unroll
        for (int j4 = 0; j4 < 16; j4++) {
            float4 o;
            o.x = Cs[row * 132 + half * 64 + j4 * 4 + 0] + bias_s[half * 64 + j4 * 4 + 0];
            o.y = Cs[row * 132 + half * 64 + j4 * 4 + 1] + bias_s[half * 64 + j4 * 4 + 1];
            o.z = Cs[row * 132 + half * 64 + j4 * 4 + 2] + bias_s[half * 64 + j4 * 4 + 2];
            o.w = Cs[row * 132 + half * 64 + j4 * 4 + 3] + bias_s[half * 64 + j4 * 4 + 3];
            *(float4*)(outp + (size_t)m * 1024 + bn + half * 64 + j4 * 4) = o;
        }
    } else {
        // mode 2: transposed write [b,h,d,t]
        const int nl = tid >> 1, mhalf = tid & 1;
        const int n = bn + nl;
        const int head = n >> 6, d = n & 63;
        const int bbk = bm >> 11;
        const float bia = bias_s[nl];
        float vals[64];
        #pragma unroll
        for (int j = 0; j < 64; j++) vals[j] = Cs[(mhalf * 64 + j) * 132 + nl] + bia;
        __nv_bfloat16* dsth = g_vthi + ((size_t)(bbk * H_ + head) * HD_ + d) * T_ + (bm & 2047) + mhalf * 64;
        __nv_bfloat16* dstl = g_vtlo + ((size_t)(bbk * H_ + head) * HD_ + d) * T_ + (bm & 2047) + mhalf * 64;
        #pragma unroll
        for (int blk = 0; blk < 8; blk++) {
            uint4 uh, ul;
            pack8(&vals[blk * 8], uh, ul);
            *(uint4*)(dsth + blk * 8) = uh;
            *(uint4*)(dstl + blk * 8) = ul;
        }
    }
}

// ---------------- gate --------------------------------------------------------
__global__ void __launch_bounds__(256) gate_kernel(const float* __restrict__ x,
                                                   const float* __restrict__ Wg,
                                                   const float* __restrict__ bg,
                                                   const float* __restrict__ gc)
{
    __shared__ float wgs[512];
    __shared__ float bgs[8];
    for (int i = threadIdx.x; i < 512; i += 256) wgs[i] = Wg[i];
    if (threadIdx.x < 8) bgs[threadIdx.x] = bg[threadIdx.x];
    __syncthreads();

    const int idx = blockIdx.x * 256 + threadIdx.x;
    const int b = idx >> 15, h = (idx >> 11) & 15, t = idx & 2047;
    const float* xr = x + ((size_t)(b * T_ + t)) * D_ + h * HD_;
    float xv[64];
    #pragma unroll
    for (int i = 0; i < 16; i++) *(float4*)&xv[i * 4] = *(const float4*)(xr + i * 4);

    float s0 = 0.f, s1 = 0.f;
    #pragma unroll
    for (int e = 0; e < 8; e++) {
        float s = bgs[e];
        #pragma unroll
        for (int d = 0; d < 64; d++) s += xv[d] * wgs[e * 64 + d];
        if (e < 4) s0 += s; else s1 += s;
    }
    const float g0 = 1.f / (1.f + __expf(-s0));
    const float g1 = 1.f / (1.f + __expf(-s1));
    g_gate[idx] = g0 * (g1 * gc[h] - 1.0f) + 2.0f;
}

// ---------------- mma.sync attention ------------------------------------------
// smem (bytes): Q hi/lo (stride 144B) @0/18432; K hi/lo @36864/55296;
// Vt hi/lo (stride 272B) @73728/91136; P hi/lo (stride 272B) @108544/143360.
#define A_Q   0
#define A_K   36864
#define A_VT  73728
#define A_P   108544
#define A_SMEM 178176

__global__ void __launch_bounds__(256) attn_mm(const float* __restrict__ pb)
{
    extern __shared__ char smc[];
    const uint32_t sb = smem_u32(smc);
    __shared__ float gate_s[128];
    __shared__ float l_smem[128];

    const int b  = blockIdx.x & 1;
    const int q0 = (blockIdx.x >> 1) * 128;
    const int h  = blockIdx.y;
    const int bh = b * H_ + h;
    const int tid = threadIdx.x, lane = tid & 31, wid = tid >> 5;
    const int wy = wid >> 2, wx = wid & 3;
    const int g = lane >> 2, tig = lane & 3;

    if (tid < 128) {
        gate_s[tid] = g_gate[bh * T_ + q0 + tid];
        l_smem[tid] = 0.f;
    }

    // Q load (cp.async, 2048 uint4)
    #pragma unroll
    for (int j = 0; j < 8; j++) {
        int c = tid + j * 256;
        int arr = c >> 10, idx = c & 1023, row = idx >> 3, sg = idx & 7;
        cpa16(sb + A_Q + arr * 18432 + row * 144 + sg * 16,
              (arr ? g_qlo : g_qhi) + ((size_t)bh * T_ + q0 + row) * HD_ + sg * 8);
    }
    CP_COMMIT();

    float oacc[4][2][4] = {};
    float l_acc[8] = {};

    for (int kb = 0; kb < 16; kb++) {
        __syncthreads();          // prior PV readers done before K/Vt overwrite
        #pragma unroll
        for (int j = 0; j < 8; j++) {     // K hi/lo
            int c = tid + j * 256;
            int arr = c >> 10, idx = c & 1023, row = idx >> 3, sg = idx & 7;
            cpa16(sb + A_K + arr * 18432 + row * 144 + sg * 16,
                  (arr ? g_klo : g_khi) + ((size_t)bh * T_ + kb * 128 + row) * HD_ + sg * 8);
        }
        #pragma unroll
        for (int j = 0; j < 8; j++) {     // Vt hi/lo
            int c = tid + j * 256;
            int arr = c >> 10, idx = c & 1023, row = idx >> 4, sg = idx & 15;
            cpa16(sb + A_VT + arr * 17408 + row * 272 + sg * 16,
                  (arr ? g_vtlo : g_vthi) + ((size_t)bh * HD_ + row) * T_ + kb * 128 + sg * 8);
        }
        CP_COMMIT(); CP_WAIT0();
        __syncthreads();

        // ---- S = Q K^T (3 products) ----
        float sacc[4][4][4] = {};
        #pragma unroll
        for (int kt = 0; kt < 4; kt++) {
            uint32_t qh[4][4], ql[4][4];
            const uint32_t arow = wy * 64 + (lane & 15);
            const uint32_t acol = (kt * 16 + (lane >> 4) * 8) * 2;
            #pragma unroll
            for (int mt = 0; mt < 4; mt++) {
                ldm4(qh[mt], sb + A_Q + (arow + mt * 16) * 144 + acol);
                ldm4(ql[mt], sb + A_Q + 18432 + (arow + mt * 16) * 144 + acol);
            }
            #pragma unroll
            for (int np = 0; np < 2; np++) {
                uint32_t kh[4], kl[4];
                const uint32_t brow = wx * 32 + np * 16 + (lane & 7) + ((lane >> 4) & 1) * 8;
                const uint32_t bcol = (kt * 16 + ((lane >> 3) & 1) * 8) * 2;
                ldm4(kh, sb + A_K + brow * 144 + bcol);
                ldm4(kl, sb + A_K + 18432 + brow * 144 + bcol);
                #pragma unroll
                for (int mt = 0; mt < 4; mt++) {
                    #pragma unroll
                    for (int hn = 0; hn < 2; hn++) {
                        const int nt = np * 2 + hn;
                        mma_bf16(sacc[mt][nt], qh[mt], kh + hn * 2);
                        mma_bf16(sacc[mt][nt], qh[mt], kl + hn * 2);
                        mma_bf16(sacc[mt][nt], ql[mt], kh + hn * 2);
                    }
                }
            }
        }

        // ---- epilogue: exp(0.125 s + gate*bias) -> split-bf16 P in smem ----
        #pragma unroll
        for (int mt = 0; mt < 4; mt++) {
            #pragma unroll
            for (int rh = 0; rh < 2; rh++) {
                const int row = wy * 64 + mt * 16 + g + rh * 8;
                const float gt = gate_s[row];
                const float* brow = pb + ((size_t)h * T_ + q0 + row) * T_ + kb * 128;
                float lsum = 0.f;
                #pragma unroll
                for (int nt = 0; nt < 4; nt++) {
                    const int col = wx * 32 + nt * 8 + tig * 2;
                    float2 bv = *(const float2*)(brow + col);
                    float p0 = __expf(sacc[mt][nt][rh * 2 + 0] * 0.125f + gt * bv.x);
                    float p1 = __expf(sacc[mt][nt][rh * 2 + 1] * 0.125f + gt * bv.y);
                    lsum += p0 + p1;
                    unsigned short h0, l0, h1, l1;
                    split2(p0, h0, l0); split2(p1, h1, l1);
                    *(uint32_t*)(smc + A_P + row * 272 + col * 2) =
                        (uint32_t)h0 | ((uint32_t)h1 << 16);
                    *(uint32_t*)(smc + A_P + 34816 + row * 272 + col * 2) =
                        (uint32_t)l0 | ((uint32_t)l1 << 16);
                }
                l_acc[mt * 2 + rh] += lsum;
            }
        }
        __syncthreads();

        // ---- O += P V (3 products) ----
        #pragma unroll
        for (int kt = 0; kt < 8; kt++) {
            uint32_t ph[4][4], pl[4][4];
            const uint32_t arow = wy * 64 + (lane & 15);
            const uint32_t acol = (kt * 16 + (lane >> 4) * 8) * 2;
            #pragma unroll
            for (int mt = 0; mt < 4; mt++) {
                ldm4(ph[mt], sb + A_P + (arow + mt * 16) * 272 + acol);
                ldm4(pl[mt], sb + A_P + 34816 + (arow + mt * 16) * 272 + acol);
            }
            uint32_t vh[4], vl[4];
            const uint32_t brow = wx * 16 + (lane & 7) + ((lane >> 4) & 1) * 8;
            const uint32_t bcol = (kt * 16 + ((lane >> 3) & 1) * 8) * 2;
            ldm4(vh, sb + A_VT + brow * 272 + bcol);
            ldm4(vl, sb + A_VT + 17408 + brow * 272 + bcol);
            #pragma unroll
            for (int mt = 0; mt < 4; mt++) {
                #pragma unroll
                for (int hn = 0; hn < 2; hn++) {
                    mma_bf16(oacc[mt][hn], ph[mt], vh + hn * 2);
                    mma_bf16(oacc[mt][hn], ph[mt], vl + hn * 2);
                    mma_bf16(oacc[mt][hn], pl[mt], vh + hn * 2);
                }
            }
        }
    }

    // ---- l reduction ----
    #pragma unroll
    for (int i = 0; i < 8; i++) {
        l_acc[i] += __shfl_xor_sync(0xffffffffu, l_acc[i], 1);
        l_acc[i] += __shfl_xor_sync(0xffffffffu, l_acc[i], 2);
    }
    __syncthreads();
    if (tig == 0) {
        #pragma unroll
        for (int mt = 0; mt < 4; mt++) {
            #pragma unroll
            for (int rh = 0; rh < 2; rh++)
                atomicAdd(&l_smem[wy * 64 + mt * 16 + g + rh * 8], l_acc[mt * 2 + rh]);
        }
    }
    __syncthreads();

    // ---- write O (split bf16) ----
    #pragma unroll
    for (int mt = 0; mt < 4; mt++) {
        #pragma unroll
        for (int rh = 0; rh < 2; rh++) {
            const int row = wy * 64 + mt * 16 + g + rh * 8;
            const float inv = 1.0f / l_smem[row];
            const size_t ro = (size_t)(b * T_ + q0 + row) * 1024 + h * 64;
            #pragma unroll
            for (int nt = 0; nt < 2; nt++) {
                const int d0 = wx * 16 + nt * 8 + tig * 2;
                float v0 = oacc[mt][nt][rh * 2 + 0] * inv;
                float v1 = oacc[mt][nt][rh * 2 + 1] * inv;
                unsigned short h0, l0, h1, l1;
                split2(v0, h0, l0); split2(v1, h1, l1);
                *(uint32_t*)(g_ohi + ro + d0) = (uint32_t)h0 | ((uint32_t)h1 << 16);
                *(uint32_t*)(g_olo + ro + d0) = (uint32_t)l0 | ((uint32_t)l1 << 16);
            }
        }
    }
}

// ---------------- launch ------------------------------------------------------
extern "C" void kernel_launch(void* const* d_in, const int* in_sizes, int n_in,
                              void* d_out, int out_size)
{
    const float* x  = (const float*)d_in[0];
    const float* pb = (const float*)d_in[1];
    const float* Wq = (const float*)d_in[2];
    const float* bq = (const float*)d_in[3];
    const float* Wk = (const float*)d_in[4];
    const float* bk = (const float*)d_in[5];
    const float* Wv = (const float*)d_in[6];
    const float* bv = (const float*)d_in[7];
    const float* Wo = (const float*)d_in[8];
    const float* bo = (const float*)d_in[9];
    const float* Wg = (const float*)d_in[10];
    const float* bg = (const float*)d_in[11];
    const float* gc = (const float*)d_in[12];
    float* out = (float*)d_out;

    cudaFuncSetAttribute(mm_gemm, cudaFuncAttributeMaxDynamicSharedMemorySize, GS_SMEM);
    cudaFuncSetAttribute(attn_mm, cudaFuncAttributeMaxDynamicSharedMemorySize, A_SMEM);

    cvt_x<<<M_*D_/1024, 256>>>(x);
    cvt_w<<<D_*D_/1024, 256>>>(Wq, 0);
    cvt_w<<<D_*D_/1024, 256>>>(Wk, 1);
    cvt_w<<<D_*D_/1024, 256>>>(Wv, 2);
    cvt_w<<<D_*D_/1024, 256>>>(Wo, 3);
    gate_kernel<<<(B_*H_*T_)/256, 256>>>(x, Wg, bg, gc);

    dim3 gg(D_/128, M_/128);
    mm_gemm<<<gg, 256, GS_SMEM>>>(bq, nullptr, 0);
    mm_gemm<<<gg, 256, GS_SMEM>>>(bk, nullptr, 1);
    mm_gemm<<<gg, 256, GS_SMEM>>>(bv, nullptr, 2);

    attn_mm<<<dim3((T_/128)*B_, H_), 256, A_SMEM>>>(pb);

    mm_gemm<<<gg, 256, GS_SMEM>>>(bo, out, 3);
}

// round 16
// speedup vs baseline: 1.8470x; 1.8449x over previous
#include <cuda_runtime.h>
#include <cuda_fp16.h>
#include <cstdint>

#define B_  2
#define T_  2048
#define D_  1024
#define H_  16
#define HD_ 64
#define M_  (B_*T_)   // 4096

// ---------------- scratch (single fp16 precision) ------------------------------
__device__ __half g_x[M_*D_];
__device__ __half g_w[4*D_*D_];
__device__ __half g_q[M_*D_];          // [b,h,t,d]
__device__ __half g_k[M_*D_];          // [b,h,t,d]
__device__ __half g_vt[M_*D_];         // [b,h,d,t]
__device__ __half g_o[M_*D_];          // [m, 1024]
__device__ float g_gate[B_*H_*T_];

// ---------------- helpers ----------------------------------------------------
__device__ __forceinline__ uint32_t smem_u32(const void* p) {
    uint32_t a;
    asm("{ .reg .u64 t; cvta.to.shared.u64 t, %1; cvt.u32.u64 %0, t; }" : "=r"(a) : "l"(p));
    return a;
}
__device__ __forceinline__ void cpa16(uint32_t dst, const void* src) {
    asm volatile("cp.async.cg.shared.global [%0], [%1], 16;" :: "r"(dst), "l"(src));
}
#define CP_COMMIT() asm volatile("cp.async.commit_group;" ::: "memory")
#define CP_WAIT0()  asm volatile("cp.async.wait_group 0;" ::: "memory")
#define CP_WAIT1()  asm volatile("cp.async.wait_group 1;" ::: "memory")

__device__ __forceinline__ void ldm4(uint32_t* r, uint32_t addr) {
    asm volatile("ldmatrix.sync.aligned.m8n8.x4.shared.b16 {%0,%1,%2,%3}, [%4];"
                 : "=r"(r[0]), "=r"(r[1]), "=r"(r[2]), "=r"(r[3]) : "r"(addr));
}
__device__ __forceinline__ void mma_f16(float* d, const uint32_t* a, const uint32_t* b) {
    asm volatile("mma.sync.aligned.m16n8k16.row.col.f32.f16.f16.f32 "
                 "{%0,%1,%2,%3}, {%4,%5,%6,%7}, {%8,%9}, {%0,%1,%2,%3};"
                 : "+f"(d[0]), "+f"(d[1]), "+f"(d[2]), "+f"(d[3])
                 : "r"(a[0]), "r"(a[1]), "r"(a[2]), "r"(a[3]), "r"(b[0]), "r"(b[1]));
}
__device__ __forceinline__ uint4 pack8h(const float* v) {
    __half2 a = __floats2half2_rn(v[0], v[1]);
    __half2 b = __floats2half2_rn(v[2], v[3]);
    __half2 c = __floats2half2_rn(v[4], v[5]);
    __half2 d = __floats2half2_rn(v[6], v[7]);
    uint4 u;
    u.x = *(uint32_t*)&a; u.y = *(uint32_t*)&b;
    u.z = *(uint32_t*)&c; u.w = *(uint32_t*)&d;
    return u;
}

// ---------------- conversions ------------------------------------------------
__global__ void __launch_bounds__(256) cvt_x(const float* __restrict__ src) {
    int i = (blockIdx.x * 256 + threadIdx.x) * 8;
    float v[8];
    *(float4*)v       = *(const float4*)(src + i);
    *(float4*)(v + 4) = *(const float4*)(src + i + 4);
    *(uint4*)(g_x + i) = pack8h(v);
}
__global__ void __launch_bounds__(256) cvt_w(const float* __restrict__ src, int w) {
    int i = (blockIdx.x * 256 + threadIdx.x) * 8;
    float v[8];
    *(float4*)v       = *(const float4*)(src + i);
    *(float4*)(v + 4) = *(const float4*)(src + i + 4);
    *(uint4*)(g_w + (size_t)w * D_ * D_ + i) = pack8h(v);
}

// ---------------- mma.sync GEMM (fp16 single product) --------------------------
// C = A @ W^T + bias.  modes: 0->g_q, 1->g_k ([b,h,t,d]),
// 2->g_vt ([b,h,d,t] transposed epilogue), 3: A:=g_o, fp32 out.
// CTA 128x128, K-chunk 64, 8 warps (wy 0-1 x wx 0-3), warp tile 64x32.
// smem tile: 128 rows x 144B (64 f16 + 8 pad).
#define GS_TILE 18432          // 128*144
#define GS_BUF  36864          // A + W
#define GS_SMEM 73728          // 2 buffers (C staging 128*132*4=67584 fits)

__global__ void __launch_bounds__(256) mm_gemm(const float* __restrict__ bias,
                                               float* __restrict__ outp, int mode)
{
    extern __shared__ char smc[];
    const uint32_t sb = smem_u32(smc);
    __shared__ float bias_s[128];

    const int bn = blockIdx.x * 128, bm = blockIdx.y * 128;
    const int tid = threadIdx.x, lane = tid & 31, wid = tid >> 5;
    const int wy = wid >> 2, wx = wid & 3;
    const int g = lane >> 2, tig = lane & 3;

    if (tid < 128) bias_s[tid] = bias[bn + tid];

    const __half* A = (mode == 3) ? g_o : g_x;
    const __half* W = g_w + (size_t)((mode == 3) ? 3 : mode) * D_ * D_;

    float acc[4][4][4] = {};

    // prologue: chunk 0 -> buffer 0   (2048 uint4 = 8 per thread)
    #pragma unroll
    for (int j = 0; j < 8; j++) {
        int c = tid + j * 256;
        int tl = c >> 10, idx = c & 1023, row = idx >> 3, sg = idx & 7;
        const __half* bp = tl ? W : A;
        int gr = (tl ? bn : bm) + row;
        cpa16(sb + tl * GS_TILE + row * 144 + sg * 16, bp + (size_t)gr * 1024 + sg * 8);
    }
    CP_COMMIT();

    for (int it = 0; it < 16; it++) {
        const int buf = it & 1;
        if (it + 1 < 16) {
            const int k0 = (it + 1) * 64;
            const int nb = buf ^ 1;
            #pragma unroll
            for (int j = 0; j < 8; j++) {
                int c = tid + j * 256;
                int tl = c >> 10, idx = c & 1023, row = idx >> 3, sg = idx & 7;
                const __half* bp = tl ? W : A;
                int gr = (tl ? bn : bm) + row;
                cpa16(sb + nb * GS_BUF + tl * GS_TILE + row * 144 + sg * 16,
                      bp + (size_t)gr * 1024 + k0 + sg * 8);
            }
            CP_COMMIT();
            CP_WAIT1();
        } else {
            CP_WAIT0();
        }
        __syncthreads();

        const uint32_t bb = sb + buf * GS_BUF;
        #pragma unroll
        for (int kt = 0; kt < 4; kt++) {
            uint32_t af[4][4];
            const uint32_t arow = wy * 64 + (lane & 15);
            const uint32_t acol = (kt * 16 + (lane >> 4) * 8) * 2;
            #pragma unroll
            for (int mt = 0; mt < 4; mt++)
                ldm4(af[mt], bb + (arow + mt * 16) * 144 + acol);
            #pragma unroll
            for (int np = 0; np < 2; np++) {
                uint32_t bf[4];
                const uint32_t brow = wx * 32 + np * 16 + (lane & 7) + ((lane >> 4) & 1) * 8;
                const uint32_t bcol = (kt * 16 + ((lane >> 3) & 1) * 8) * 2;
                ldm4(bf, bb + GS_TILE + brow * 144 + bcol);
                #pragma unroll
                for (int mt = 0; mt < 4; mt++) {
                    mma_f16(acc[mt][np * 2 + 0], af[mt], bf + 0);
                    mma_f16(acc[mt][np * 2 + 1], af[mt], bf + 2);
                }
            }
        }
        __syncthreads();
    }

    // ---- stage C (fp32, stride 132) ----
    float* Cs = (float*)smc;
    #pragma unroll
    for (int mt = 0; mt < 4; mt++) {
        const int r0 = wy * 64 + mt * 16 + g;
        #pragma unroll
        for (int nt = 0; nt < 4; nt++) {
            const int cc = wx * 32 + nt * 8 + tig * 2;
            *(float2*)(Cs + r0 * 132 + cc)       = make_float2(acc[mt][nt][0], acc[mt][nt][1]);
            *(float2*)(Cs + (r0 + 8) * 132 + cc) = make_float2(acc[mt][nt][2], acc[mt][nt][3]);
        }
    }
    __syncthreads();

    if (mode <= 1) {
        __half* dq = (mode == 0) ? g_q : g_k;
        const int row = tid >> 1, half = tid & 1;
        const int m = bm + row;
        const int bbk = m >> 11, t = m & 2047;
        const int head = (bn >> 6) + half;
        const size_t ro = ((size_t)(bbk * H_ + head) * T_ + t) * HD_;
        float vals[64];
        #pragma unroll
        for (int j = 0; j < 64; j++) vals[j] = Cs[row * 132 + half * 64 + j] + bias_s[half * 64 + j];
        #pragma unroll
        for (int blk = 0; blk < 8; blk++)
            *(uint4*)(dq + ro + blk * 8) = pack8h(&vals[blk * 8]);
    } else if (mode == 3) {
        const int row = tid >> 1, half = tid & 1;
        const int m = bm + row;
        #pragma unroll
        for (int j4 = 0; j4 < 16; j4++) {
            float4 o;
            o.x = Cs[row * 132 + half * 64 + j4 * 4 + 0] + bias_s[half * 64 + j4 * 4 + 0];
            o.y = Cs[row * 132 + half * 64 + j4 * 4 + 1] + bias_s[half * 64 + j4 * 4 + 1];
            o.z = Cs[row * 132 + half * 64 + j4 * 4 + 2] + bias_s[half * 64 + j4 * 4 + 2];
            o.w = Cs[row * 132 + half * 64 + j4 * 4 + 3] + bias_s[half * 64 + j4 * 4 + 3];
            *(float4*)(outp + (size_t)m * 1024 + bn + half * 64 + j4 * 4) = o;
        }
    } else {
        // mode 2: transposed write [b,h,d,t]
        const int nl = tid >> 1, mhalf = tid & 1;
        const int n = bn + nl;
        const int head = n >> 6, d = n & 63;
        const int bbk = bm >> 11;
        const float bia = bias_s[nl];
        float vals[64];
        #pragma unroll
        for (int j = 0; j < 64; j++) vals[j] = Cs[(mhalf * 64 + j) * 132 + nl] + bia;
        __half* dst = g_vt + ((size_t)(bbk * H_ + head) * HD_ + d) * T_ + (bm & 2047) + mhalf * 64;
        #pragma unroll
        for (int blk = 0; blk < 8; blk++)
            *(uint4*)(dst + blk * 8) = pack8h(&vals[blk * 8]);
    }
}

// ---------------- gate --------------------------------------------------------
__global__ void __launch_bounds__(256) gate_kernel(const float* __restrict__ x,
                                                   const float* __restrict__ Wg,
                                                   const float* __restrict__ bg,
                                                   const float* __restrict__ gc)
{
    __shared__ float wgs[512];
    __shared__ float bgs[8];
    for (int i = threadIdx.x; i < 512; i += 256) wgs[i] = Wg[i];
    if (threadIdx.x < 8) bgs[threadIdx.x] = bg[threadIdx.x];
    __syncthreads();

    const int idx = blockIdx.x * 256 + threadIdx.x;
    const int b = idx >> 15, h = (idx >> 11) & 15, t = idx & 2047;
    const float* xr = x + ((size_t)(b * T_ + t)) * D_ + h * HD_;
    float xv[64];
    #pragma unroll
    for (int i = 0; i < 16; i++) *(float4*)&xv[i * 4] = *(const float4*)(xr + i * 4);

    float s0 = 0.f, s1 = 0.f;
    #pragma unroll
    for (int e = 0; e < 8; e++) {
        float s = bgs[e];
        #pragma unroll
        for (int d = 0; d < 64; d++) s += xv[d] * wgs[e * 64 + d];
        if (e < 4) s0 += s; else s1 += s;
    }
    const float g0 = 1.f / (1.f + __expf(-s0));
    const float g1 = 1.f / (1.f + __expf(-s1));
    g_gate[idx] = g0 * (g1 * gc[h] - 1.0f) + 2.0f;
}

// ---------------- mma.sync attention (fp16 single product) ---------------------
// smem: Q (128x144B) @0; K @18432; Vt (64x272B) @36864; P (128x272B) @54272.
#define A_Q   0
#define A_K   18432
#define A_VT  36864
#define A_P   54272
#define A_SMEM 89088

__global__ void __launch_bounds__(256) attn_mm(const float* __restrict__ pb)
{
    extern __shared__ char smc[];
    const uint32_t sb = smem_u32(smc);
    __shared__ float gate_s[128];
    __shared__ float l_smem[128];

    const int b  = blockIdx.x & 1;
    const int q0 = (blockIdx.x >> 1) * 128;
    const int h  = blockIdx.y;
    const int bh = b * H_ + h;
    const int tid = threadIdx.x, lane = tid & 31, wid = tid >> 5;
    const int wy = wid >> 2, wx = wid & 3;
    const int g = lane >> 2, tig = lane & 3;

    if (tid < 128) {
        gate_s[tid] = g_gate[bh * T_ + q0 + tid];
        l_smem[tid] = 0.f;
    }

    // Q load (1024 uint4 = 4 per thread)
    #pragma unroll
    for (int j = 0; j < 4; j++) {
        int c = tid + j * 256;
        int row = c >> 3, sg = c & 7;
        cpa16(sb + A_Q + row * 144 + sg * 16,
              g_q + ((size_t)bh * T_ + q0 + row) * HD_ + sg * 8);
    }
    CP_COMMIT();

    float oacc[4][2][4] = {};
    float l_acc[8] = {};

    for (int kb = 0; kb < 16; kb++) {
        __syncthreads();          // prior PV readers done before K/Vt/P overwrite
        #pragma unroll
        for (int j = 0; j < 4; j++) {     // K: 1024 uint4
            int c = tid + j * 256;
            int row = c >> 3, sg = c & 7;
            cpa16(sb + A_K + row * 144 + sg * 16,
                  g_k + ((size_t)bh * T_ + kb * 128 + row) * HD_ + sg * 8);
        }
        #pragma unroll
        for (int j = 0; j < 4; j++) {     // Vt: 1024 uint4
            int c = tid + j * 256;
            int row = c >> 4, sg = c & 15;
            cpa16(sb + A_VT + row * 272 + sg * 16,
                  g_vt + ((size_t)bh * HD_ + row) * T_ + kb * 128 + sg * 8);
        }
        CP_COMMIT(); CP_WAIT0();
        __syncthreads();

        // ---- S = Q K^T ----
        float sacc[4][4][4] = {};
        #pragma unroll
        for (int kt = 0; kt < 4; kt++) {
            uint32_t qf[4][4];
            const uint32_t arow = wy * 64 + (lane & 15);
            const uint32_t acol = (kt * 16 + (lane >> 4) * 8) * 2;
            #pragma unroll
            for (int mt = 0; mt < 4; mt++)
                ldm4(qf[mt], sb + A_Q + (arow + mt * 16) * 144 + acol);
            #pragma unroll
            for (int np = 0; np < 2; np++) {
                uint32_t kf[4];
                const uint32_t brow = wx * 32 + np * 16 + (lane & 7) + ((lane >> 4) & 1) * 8;
                const uint32_t bcol = (kt * 16 + ((lane >> 3) & 1) * 8) * 2;
                ldm4(kf, sb + A_K + brow * 144 + bcol);
                #pragma unroll
                for (int mt = 0; mt < 4; mt++) {
                    mma_f16(sacc[mt][np * 2 + 0], qf[mt], kf + 0);
                    mma_f16(sacc[mt][np * 2 + 1], qf[mt], kf + 2);
                }
            }
        }

        // ---- epilogue: exp(0.125 s + gate*bias) -> f16 P in smem ----
        #pragma unroll
        for (int mt = 0; mt < 4; mt++) {
            #pragma unroll
            for (int rh = 0; rh < 2; rh++) {
                const int row = wy * 64 + mt * 16 + g + rh * 8;
                const float gt = gate_s[row];
                const float* brow = pb + ((size_t)h * T_ + q0 + row) * T_ + kb * 128;
                float lsum = 0.f;
                #pragma unroll
                for (int nt = 0; nt < 4; nt++) {
                    const int col = wx * 32 + nt * 8 + tig * 2;
                    float2 bv = *(const float2*)(brow + col);
                    float p0 = __expf(sacc[mt][nt][rh * 2 + 0] * 0.125f + gt * bv.x);
                    float p1 = __expf(sacc[mt][nt][rh * 2 + 1] * 0.125f + gt * bv.y);
                    __half2 ph = __floats2half2_rn(p0, p1);
                    *(uint32_t*)(smc + A_P + row * 272 + col * 2) = *(uint32_t*)&ph;
                    float2 pr = __half22float2(ph);   // l from rounded P (common-mode cancel)
                    lsum += pr.x + pr.y;
                }
                l_acc[mt * 2 + rh] += lsum;
            }
        }
        __syncthreads();

        // ---- O += P V ----
        #pragma unroll
        for (int kt = 0; kt < 8; kt++) {
            uint32_t pf[4][4];
            const uint32_t arow = wy * 64 + (lane & 15);
            const uint32_t acol = (kt * 16 + (lane >> 4) * 8) * 2;
            #pragma unroll
            for (int mt = 0; mt < 4; mt++)
                ldm4(pf[mt], sb + A_P + (arow + mt * 16) * 272 + acol);
            uint32_t vf[4];
            const uint32_t brow = wx * 16 + (lane & 7) + ((lane >> 4) & 1) * 8;
            const uint32_t bcol = (kt * 16 + ((lane >> 3) & 1) * 8) * 2;
            ldm4(vf, sb + A_VT + brow * 272 + bcol);
            #pragma unroll
            for (int mt = 0; mt < 4; mt++) {
                mma_f16(oacc[mt][0], pf[mt], vf + 0);
                mma_f16(oacc[mt][1], pf[mt], vf + 2);
            }
        }
    }

    // ---- l reduction ----
    #pragma unroll
    for (int i = 0; i < 8; i++) {
        l_acc[i] += __shfl_xor_sync(0xffffffffu, l_acc[i], 1);
        l_acc[i] += __shfl_xor_sync(0xffffffffu, l_acc[i], 2);
    }
    __syncthreads();
    if (tig == 0) {
        #pragma unroll
        for (int mt = 0; mt < 4; mt++) {
            #pragma unroll
            for (int rh = 0; rh < 2; rh++)
                atomicAdd(&l_smem[wy * 64 + mt * 16 + g + rh * 8], l_acc[mt * 2 + rh]);
        }
    }
    __syncthreads();

    // ---- write O (f16) ----
    #pragma unroll
    for (int mt = 0; mt < 4; mt++) {
        #pragma unroll
        for (int rh = 0; rh < 2; rh++) {
            const int row = wy * 64 + mt * 16 + g + rh * 8;
            const float inv = 1.0f / l_smem[row];
            const size_t ro = (size_t)(b * T_ + q0 + row) * 1024 + h * 64;
            #pragma unroll
            for (int nt = 0; nt < 2; nt++) {
                const int d0 = wx * 16 + nt * 8 + tig * 2;
                __half2 o2 = __floats2half2_rn(oacc[mt][nt][rh * 2 + 0] * inv,
                                               oacc[mt][nt][rh * 2 + 1] * inv);
                *(uint32_t*)(g_o + ro + d0) = *(uint32_t*)&o2;
            }
        }
    }
}

// ---------------- launch ------------------------------------------------------
extern "C" void kernel_launch(void* const* d_in, const int* in_sizes, int n_in,
                              void* d_out, int out_size)
{
    const float* x  = (const float*)d_in[0];
    const float* pb = (const float*)d_in[1];
    const float* Wq = (const float*)d_in[2];
    const float* bq = (const float*)d_in[3];
    const float* Wk = (const float*)d_in[4];
    const float* bk = (const float*)d_in[5];
    const float* Wv = (const float*)d_in[6];
    const float* bv = (const float*)d_in[7];
    const float* Wo = (const float*)d_in[8];
    const float* bo = (const float*)d_in[9];
    const float* Wg = (const float*)d_in[10];
    const float* bg = (const float*)d_in[11];
    const float* gc = (const float*)d_in[12];
    float* out = (float*)d_out;

    cudaFuncSetAttribute(mm_gemm, cudaFuncAttributeMaxDynamicSharedMemorySize, GS_SMEM);
    cudaFuncSetAttribute(attn_mm, cudaFuncAttributeMaxDynamicSharedMemorySize, A_SMEM);

    cvt_x<<<M_*D_/2048, 256>>>(x);
    cvt_w<<<D_*D_/2048, 256>>>(Wq, 0);
    cvt_w<<<D_*D_/2048, 256>>>(Wk, 1);
    cvt_w<<<D_*D_/2048, 256>>>(Wv, 2);
    cvt_w<<<D_*D_/2048, 256>>>(Wo, 3);
    gate_kernel<<<(B_*H_*T_)/256, 256>>>(x, Wg, bg, gc);

    dim3 gg(D_/128, M_/128);
    mm_gemm<<<gg, 256, GS_SMEM>>>(bq, nullptr, 0);
    mm_gemm<<<gg, 256, GS_SMEM>>>(bk, nullptr, 1);
    mm_gemm<<<gg, 256, GS_SMEM>>>(bv, nullptr, 2);

    attn_mm<<<dim3((T_/128)*B_, H_), 256, A_SMEM>>>(pb);

    mm_gemm<<<gg, 256, GS_SMEM>>>(bo, out, 3);
}